// round 11
// baseline (speedup 1.0000x reference)
#include <cuda_runtime.h>
#include <cstdint>

#define NC 32
#define NSTEPS 32
#define DDIM 30
#define NBIN 16384            // bins; power of two so x*NBIN and fractions are exact
#define NTHETA_MAX 16
#define LIST_CAP (NTHETA_MAX * 300000)

__device__ float    g_F[NTHETA_MAX][NBIN + 1];   // flow map at grid points
__device__ uint32_t g_h[NTHETA_MAX][NBIN + 1];   // hash of 32-step cell sequence
__device__ float2   g_coefd[NTHETA_MAX][33];     // per-(theta,cell) affine coefs
__device__ uint32_t g_cnt;                       // unsafe-point counter
__device__ uint32_t g_list[LIST_CAP];            // packed (theta<<28 | point idx)

// ============================================================
// Kernel 1: build F + sequence hashes at grid points
// ============================================================
#define BTPB 256
#define BPPT 4

__global__ __launch_bounds__(BTPB) void build_kernel(
    const float* __restrict__ theta,
    const float* __restrict__ basis)
{
    __shared__ float2 tab[33 * 32];   // lane-replicated; cell 32 dup of 31
    __shared__ float2 coef[NC];

    const int t   = blockIdx.y;
    const int tid = threadIdx.x;

    if (blockIdx.x == 0 && blockIdx.y == 0 && tid == 0) g_cnt = 0;

    if (tid < NC) {
        const int c = tid;
        const float* __restrict__ th = theta + t * DDIM;
        const float* __restrict__ ba = basis + (2 * c) * DDIM;
        const float* __restrict__ bb = basis + (2 * c + 1) * DDIM;
        float a = 0.0f, b = 0.0f;
        #pragma unroll
        for (int j = 0; j < DDIM; j++) {
            a = fmaf(ba[j], th[j], a);
            b = fmaf(bb[j], th[j], b);
        }
        const float dT = 1.0f / (float)NSTEPS;
        float ad = dT * a;
        float bd = dT * b;
        float phi = (fabsf(ad) < 1e-6f) ? (1.0f + 0.5f * ad) : (expm1f(ad) / ad);
        coef[c] = make_float2(expf(ad), bd * phi);
    }
    __syncthreads();

    if (blockIdx.x == 0 && tid < 33)
        g_coefd[t][tid] = coef[tid > 31 ? 31 : tid];

    #pragma unroll
    for (int i = tid; i < 33 * 32; i += BTPB) {
        int c = i >> 5;
        tab[i] = coef[c > 31 ? 31 : c];
    }
    __syncthreads();

    const int lane = tid & 31;
    const uint32_t sbase =
        (uint32_t)__cvta_generic_to_shared(tab) + (uint32_t)(lane * 8);

    const int g0 = blockIdx.x * (BTPB * BPPT) + tid;

    float x[BPPT];
    uint32_t h[BPPT];
    #pragma unroll
    for (int k = 0; k < BPPT; k++) {
        x[k] = (float)(g0 + k * BTPB) * (1.0f / (float)NBIN);  // exact
        h[k] = 0u;
    }

    #pragma unroll 2
    for (int s = 0; s < NSTEPS; s++) {
        #pragma unroll
        for (int k = 0; k < BPPT; k++) {
            float v = __saturatef(x[k]);
            float u;
            asm("fma.rz.f32 %0, %1, 0f42000000, 0f4B000000;" : "=f"(u) : "f"(v));
            uint32_t bits = (uint32_t)__float_as_int(u);       // 0x4B000000 + cell
            h[k] = h[k] * 2654435761u + bits;                  // sequence hash
            uint32_t addr = sbase + (bits << 8);
            float ea, bp;
            asm("ld.shared.v2.f32 {%0, %1}, [%2];"
                : "=f"(ea), "=f"(bp) : "r"(addr));
            x[k] = fmaf(ea, x[k], bp);
        }
    }

    #pragma unroll
    for (int k = 0; k < BPPT; k++) {
        int g = g0 + k * BTPB;
        if (g <= NBIN) { g_F[t][g] = x[k]; g_h[t][g] = h[k]; }
    }
}

// ============================================================
// Kernel 2: interpolate all points; push unsafe ones to a list
// ============================================================
#define ETPB 256
#define EPPT 8

__global__ __launch_bounds__(ETPB) void eval_kernel(
    const float4* __restrict__ points4,
    float4* __restrict__ out4,
    int n_points)
{
    const int t = blockIdx.y;
    const float*    __restrict__ Ft = g_F[t];
    const uint32_t* __restrict__ Ht = g_h[t];

    const int lane = threadIdx.x & 31;
    const int f4 = blockIdx.x * (ETPB * 2) + threadIdx.x * 2;
    float4 p0 = points4[f4];
    float4 p1 = points4[f4 + 1];

    float x[EPPT];
    x[0] = p0.x;  x[1] = p0.y;  x[2] = p0.z;  x[3] = p0.w;
    x[4] = p1.x;  x[5] = p1.y;  x[6] = p1.z;  x[7] = p1.w;

    const uint32_t pbase = (uint32_t)(f4 * 4) | ((uint32_t)t << 28);

    float r[EPPT];
    #pragma unroll
    for (int k = 0; k < EPPT; k++) {
        float u = x[k] * (float)NBIN;            // exact (*2^14)
        int bin = (int)u;
        bin = min(bin, NBIN - 1);
        float tt = u - (float)bin;               // exact fraction
        float F0 = __ldg(Ft + bin);
        float F1 = __ldg(Ft + bin + 1);
        r[k] = fmaf(tt, F1 - F0, F0);

        bool unsafe = (__ldg(Ht + bin) != __ldg(Ht + bin + 1));
        unsigned m = __ballot_sync(0xffffffffu, unsafe);
        if (m) {
            int leader = __ffs(m) - 1;
            uint32_t base = 0;
            if (lane == leader) base = atomicAdd(&g_cnt, (uint32_t)__popc(m));
            base = __shfl_sync(0xffffffffu, base, leader);
            if (unsafe) {
                uint32_t slot = base + __popc(m & ((1u << lane) - 1u));
                if (slot < LIST_CAP) g_list[slot] = pbase + (uint32_t)k;
            }
        }
    }

    float4 o0, o1;
    o0.x = r[0];  o0.y = r[1];  o0.z = r[2];  o0.w = r[3];
    o1.x = r[4];  o1.y = r[5];  o1.z = r[6];  o1.w = r[7];

    float4* __restrict__ op = out4 + ((size_t)t * n_points) / 4;
    op[f4]     = o0;
    op[f4 + 1] = o1;
}

// ============================================================
// Kernel 3: exact 32-step recurrence for unsafe points
// ============================================================
#define FTPB 256

__global__ __launch_bounds__(FTPB) void fixup_kernel(
    const float* __restrict__ points,
    float* __restrict__ out,
    int n_points)
{
    __shared__ float2 scoef[NTHETA_MAX * 33];
    for (int i = threadIdx.x; i < NTHETA_MAX * 33; i += FTPB)
        scoef[i] = g_coefd[i / 33][i % 33];
    __syncthreads();

    const uint32_t n = g_cnt < LIST_CAP ? g_cnt : LIST_CAP;
    const uint32_t stride = gridDim.x * FTPB;

    for (uint32_t j = blockIdx.x * FTPB + threadIdx.x; j < n; j += stride) {
        uint32_t e = g_list[j];
        int t = (int)(e >> 28);
        int i = (int)(e & 0x0FFFFFFFu);
        float x = points[i];
        const float2* __restrict__ ct = scoef + t * 33;
        #pragma unroll
        for (int s = 0; s < NSTEPS; s++) {
            float v = __saturatef(x);
            float u;
            asm("fma.rz.f32 %0, %1, 0f42000000, 0f4B000000;" : "=f"(u) : "f"(v));
            int cell = __float_as_int(u) & 63;
            float2 c = ct[cell];
            x = fmaf(c.x, x, c.y);
        }
        out[(size_t)t * n_points + i] = x;
    }
}

extern "C" void kernel_launch(void* const* d_in, const int* in_sizes, int n_in,
                              void* d_out, int out_size) {
    const float* points = (const float*)d_in[0];   // [1, n_points]
    const float* theta  = (const float*)d_in[1];   // [n_theta, 30]
    const float* basis  = (const float*)d_in[2];   // [64, 30]
    float* out = (float*)d_out;                    // [n_theta, 1, n_points]

    const int n_points = in_sizes[0];
    const int n_theta  = in_sizes[1] / DDIM;

    dim3 bgrid((NBIN + 1 + BTPB * BPPT - 1) / (BTPB * BPPT), n_theta);
    build_kernel<<<bgrid, BTPB>>>(theta, basis);

    dim3 egrid(n_points / (ETPB * EPPT), n_theta);
    eval_kernel<<<egrid, ETPB>>>((const float4*)points, (float4*)out, n_points);

    fixup_kernel<<<512, FTPB>>>(points, out, n_points);
}

// round 12
// speedup vs baseline: 2.7620x; 2.7620x over previous
#include <cuda_runtime.h>
#include <cstdint>

#define NC 32
#define NSTEPS 32
#define DDIM 30
#define NBIN 16384            // power of two: x*NBIN and fractions exact
#define NTHETA_MAX 16

// E[t][g]: .x = F(g/NBIN) as f32 bits; .y = bf16(dF)<<16 | unsafe_flag
__device__ uint2  g_E[NTHETA_MAX][NBIN + 1];
__device__ float2 g_coefd[NTHETA_MAX][33];   // per-(theta,cell) affine coefs

// ============================================================
// Kernel 1: build E (both endpoints per thread, hash-compare)
// ============================================================
#define BTPB 256

__global__ __launch_bounds__(BTPB) void build_kernel(
    const float* __restrict__ theta,
    const float* __restrict__ basis)
{
    __shared__ float2 tab[33 * 32];
    __shared__ float2 coef[NC];

    const int t   = blockIdx.y;
    const int tid = threadIdx.x;

    if (tid < NC) {
        const int c = tid;
        const float* __restrict__ th = theta + t * DDIM;
        const float* __restrict__ ba = basis + (2 * c) * DDIM;
        const float* __restrict__ bb = basis + (2 * c + 1) * DDIM;
        float a = 0.0f, b = 0.0f;
        #pragma unroll
        for (int j = 0; j < DDIM; j++) {
            a = fmaf(ba[j], th[j], a);
            b = fmaf(bb[j], th[j], b);
        }
        const float dT = 1.0f / (float)NSTEPS;
        float ad = dT * a;
        float bd = dT * b;
        float phi = (fabsf(ad) < 1e-6f) ? (1.0f + 0.5f * ad) : (expm1f(ad) / ad);
        coef[c] = make_float2(expf(ad), bd * phi);
    }
    __syncthreads();

    if (blockIdx.x == 0 && tid < 33)
        g_coefd[t][tid] = coef[tid > 31 ? 31 : tid];

    #pragma unroll
    for (int i = tid; i < 33 * 32; i += BTPB) {
        int c = i >> 5;
        tab[i] = coef[c > 31 ? 31 : c];
    }
    __syncthreads();

    const int lane = tid & 31;
    const uint32_t sbase =
        (uint32_t)__cvta_generic_to_shared(tab) + (uint32_t)(lane * 8);

    int g = blockIdx.x * BTPB + tid;
    if (g > NBIN) g = NBIN;

    float x0 = (float)g       * (1.0f / (float)NBIN);   // exact
    float x1 = (float)(g + 1) * (1.0f / (float)NBIN);
    uint32_t h0 = 0u, h1 = 0u;

    #pragma unroll 4
    for (int s = 0; s < NSTEPS; s++) {
        {   float v = __saturatef(x0);
            float u;
            asm("fma.rz.f32 %0, %1, 0f42000000, 0f4B000000;" : "=f"(u) : "f"(v));
            uint32_t bits = (uint32_t)__float_as_int(u);
            h0 = h0 * 2654435761u + bits;
            float ea, bp;
            asm("ld.shared.v2.f32 {%0, %1}, [%2];"
                : "=f"(ea), "=f"(bp) : "r"(sbase + (bits << 8)));
            x0 = fmaf(ea, x0, bp);
        }
        {   float v = __saturatef(x1);
            float u;
            asm("fma.rz.f32 %0, %1, 0f42000000, 0f4B000000;" : "=f"(u) : "f"(v));
            uint32_t bits = (uint32_t)__float_as_int(u);
            h1 = h1 * 2654435761u + bits;
            float ea, bp;
            asm("ld.shared.v2.f32 {%0, %1}, [%2];"
                : "=f"(ea), "=f"(bp) : "r"(sbase + (bits << 8)));
            x1 = fmaf(ea, x1, bp);
        }
    }

    float dF = x1 - x0;
    uint32_t dfb;
    uint32_t flag;
    if (g == NBIN) { dfb = 0u; flag = 0u; }
    else {
        dfb  = (__float_as_uint(dF) + 0x8000u) & 0xFFFF0000u;  // round to bf16
        flag = (h0 != h1) ? 1u : 0u;
    }
    g_E[t][g] = make_uint2(__float_as_uint(x0), dfb | flag);
}

// ============================================================
// Kernel 2: interpolate + in-block exact fixup for unsafe points
// ============================================================
#define ETPB 256
#define EPPT 8

__global__ __launch_bounds__(ETPB) void eval_kernel(
    const float4* __restrict__ points4,
    const float* __restrict__ points,
    float4* __restrict__ out4,
    float* __restrict__ out,
    int n_points)
{
    __shared__ float2  tab[33 * 32];
    __shared__ uint32_t slist[ETPB * EPPT];
    __shared__ uint32_t scnt;

    const int t    = blockIdx.y;
    const int tid  = threadIdx.x;
    const int lane = tid & 31;

    // lane-replicated coef table (for the fixup loop)
    #pragma unroll
    for (int i = tid; i < 33 * 32; i += ETPB)
        tab[i] = g_coefd[t][i >> 5];
    if (tid == 0) scnt = 0u;
    __syncthreads();

    const uint2* __restrict__ Et = g_E[t];

    const int f4 = blockIdx.x * (ETPB * 2) + tid * 2;
    float4 p0 = points4[f4];
    float4 p1 = points4[f4 + 1];

    float x[EPPT];
    x[0] = p0.x;  x[1] = p0.y;  x[2] = p0.z;  x[3] = p0.w;
    x[4] = p1.x;  x[5] = p1.y;  x[6] = p1.z;  x[7] = p1.w;

    const uint32_t pbase = (uint32_t)(f4 * 4);

    float r[EPPT];
    #pragma unroll
    for (int k = 0; k < EPPT; k++) {
        float v = __saturatef(x[k]);
        float w;
        asm("fma.rz.f32 %0, %1, 0f46800000, 0f4B000000;" : "=f"(w) : "f"(v));
        uint32_t bits = (uint32_t)__float_as_int(w);   // 0x4B000000 + bin
        uint32_t bin  = bits & 0x7FFFu;
        uint2 e = __ldg(Et + bin);
        float F0 = __uint_as_float(e.x);
        float dF = __uint_as_float(e.y & 0xFFFF0000u);
        float binf = w - 8388608.0f;                   // (float)bin, exact
        float tt = fmaf(v, 16384.0f, -binf);           // exact fraction
        r[k] = fmaf(tt, dF, F0);

        bool unsafe = (e.y & 1u) != 0u;
        unsigned m = __ballot_sync(0xffffffffu, unsafe);
        if (m) {
            int leader = __ffs(m) - 1;
            uint32_t b = 0;
            if (lane == leader) b = atomicAdd(&scnt, (uint32_t)__popc(m));
            b = __shfl_sync(0xffffffffu, b, leader);
            if (unsafe)
                slist[b + __popc(m & ((1u << lane) - 1u))] = pbase + (uint32_t)k;
        }
    }

    float4 o0, o1;
    o0.x = r[0];  o0.y = r[1];  o0.z = r[2];  o0.w = r[3];
    o1.x = r[4];  o1.y = r[5];  o1.z = r[6];  o1.w = r[7];
    float4* __restrict__ op = out4 + ((size_t)t * n_points) / 4;
    op[f4]     = o0;
    op[f4 + 1] = o1;

    __syncthreads();

    // exact 32-step recurrence for this block's unsafe points
    const uint32_t n = scnt;
    const uint32_t sbase =
        (uint32_t)__cvta_generic_to_shared(tab) + (uint32_t)(lane * 8);

    for (uint32_t j = tid; j < n; j += ETPB) {
        uint32_t i = slist[j];
        float xx = __ldg(points + i);
        #pragma unroll
        for (int s = 0; s < NSTEPS; s++) {
            float v = __saturatef(xx);
            float u;
            asm("fma.rz.f32 %0, %1, 0f42000000, 0f4B000000;" : "=f"(u) : "f"(v));
            uint32_t bits = (uint32_t)__float_as_int(u);
            float ea, bp;
            asm("ld.shared.v2.f32 {%0, %1}, [%2];"
                : "=f"(ea), "=f"(bp) : "r"(sbase + (bits << 8)));
            xx = fmaf(ea, xx, bp);
        }
        out[(size_t)t * n_points + i] = xx;
    }
}

extern "C" void kernel_launch(void* const* d_in, const int* in_sizes, int n_in,
                              void* d_out, int out_size) {
    const float* points = (const float*)d_in[0];   // [1, n_points]
    const float* theta  = (const float*)d_in[1];   // [n_theta, 30]
    const float* basis  = (const float*)d_in[2];   // [64, 30]
    float* out = (float*)d_out;                    // [n_theta, 1, n_points]

    const int n_points = in_sizes[0];
    const int n_theta  = in_sizes[1] / DDIM;

    dim3 bgrid((NBIN + 1 + BTPB - 1) / BTPB, n_theta);
    build_kernel<<<bgrid, BTPB>>>(theta, basis);

    dim3 egrid(n_points / (ETPB * EPPT), n_theta);
    eval_kernel<<<egrid, ETPB>>>((const float4*)points, points,
                                 (float4*)out, out, n_points);
}

// round 14
// speedup vs baseline: 2.7928x; 1.0111x over previous
#include <cuda_runtime.h>
#include <cstdint>

#define NC 32
#define NSTEPS 32
#define DDIM 30
#define NBIN 16384            // power of two: x*NBIN and fractions exact
#define NTHETA_MAX 16

// E[t][g]: .x = F(g/NBIN) as f32 bits; .y = bf16(dF)<<16 | unsafe_flag
__device__ uint2  g_E[NTHETA_MAX][NBIN + 1];
__device__ float2 g_coefd[NTHETA_MAX][33];   // per-(theta,cell) affine coefs

// ============================================================
// Kernel 1: build E (both endpoints per thread, hash-compare)
// ============================================================
#define BTPB 256

__global__ __launch_bounds__(BTPB) void build_kernel(
    const float* __restrict__ theta,
    const float* __restrict__ basis)
{
    __shared__ float2 tab[33 * 32];
    __shared__ float2 coef[NC];

    const int t   = blockIdx.y;
    const int tid = threadIdx.x;

    if (tid < NC) {
        const int c = tid;
        const float* __restrict__ th = theta + t * DDIM;
        const float* __restrict__ ba = basis + (2 * c) * DDIM;
        const float* __restrict__ bb = basis + (2 * c + 1) * DDIM;
        float a = 0.0f, b = 0.0f;
        #pragma unroll
        for (int j = 0; j < DDIM; j++) {
            a = fmaf(ba[j], th[j], a);
            b = fmaf(bb[j], th[j], b);
        }
        const float dT = 1.0f / (float)NSTEPS;
        float ad = dT * a;
        float bd = dT * b;
        float phi = (fabsf(ad) < 1e-6f) ? (1.0f + 0.5f * ad) : (expm1f(ad) / ad);
        coef[c] = make_float2(expf(ad), bd * phi);
    }
    __syncthreads();

    if (blockIdx.x == 0 && tid < 33)
        g_coefd[t][tid] = coef[tid > 31 ? 31 : tid];

    #pragma unroll
    for (int i = tid; i < 33 * 32; i += BTPB) {
        int c = i >> 5;
        tab[i] = coef[c > 31 ? 31 : c];
    }
    __syncthreads();

    const int lane = tid & 31;
    const uint32_t sbase =
        (uint32_t)__cvta_generic_to_shared(tab) + (uint32_t)(lane * 8);

    int g = blockIdx.x * BTPB + tid;
    if (g > NBIN) g = NBIN;

    float x0 = (float)g       * (1.0f / (float)NBIN);   // exact
    float x1 = (float)(g + 1) * (1.0f / (float)NBIN);
    uint32_t h0 = 0u, h1 = 0u;

    #pragma unroll 4
    for (int s = 0; s < NSTEPS; s++) {
        {   float v = __saturatef(x0);
            float u;
            asm("fma.rz.f32 %0, %1, 0f42000000, 0f4B000000;" : "=f"(u) : "f"(v));
            uint32_t bits = (uint32_t)__float_as_int(u);
            h0 = h0 * 2654435761u + bits;
            float ea, bp;
            asm("ld.shared.v2.f32 {%0, %1}, [%2];"
                : "=f"(ea), "=f"(bp) : "r"(sbase + (bits << 8)));
            x0 = fmaf(ea, x0, bp);
        }
        {   float v = __saturatef(x1);
            float u;
            asm("fma.rz.f32 %0, %1, 0f42000000, 0f4B000000;" : "=f"(u) : "f"(v));
            uint32_t bits = (uint32_t)__float_as_int(u);
            h1 = h1 * 2654435761u + bits;
            float ea, bp;
            asm("ld.shared.v2.f32 {%0, %1}, [%2];"
                : "=f"(ea), "=f"(bp) : "r"(sbase + (bits << 8)));
            x1 = fmaf(ea, x1, bp);
        }
    }

    float dF = x1 - x0;
    uint32_t dfb, flag;
    if (g == NBIN) { dfb = 0u; flag = 0u; }
    else {
        dfb  = (__float_as_uint(dF) + 0x8000u) & 0xFFFF0000u;  // round to bf16
        flag = (h0 != h1) ? 1u : 0u;
    }
    g_E[t][g] = make_uint2(__float_as_uint(x0), dfb | flag);
}

// ============================================================
// Kernel 2: interpolate (MLP=8) + in-block exact fixup
// ============================================================
#define ETPB 256
#define EPPT 8

__global__ __launch_bounds__(ETPB) void eval_kernel(
    const float4* __restrict__ points4,
    const float* __restrict__ points,
    float4* __restrict__ out4,
    float* __restrict__ out,
    int n_points)
{
    __shared__ float2   tab[33 * 32];
    __shared__ uint32_t slist[ETPB * EPPT];
    __shared__ uint32_t scnt;

    const int t    = blockIdx.y;
    const int tid  = threadIdx.x;
    const int lane = tid & 31;

    #pragma unroll
    for (int i = tid; i < 33 * 32; i += ETPB)
        tab[i] = g_coefd[t][i >> 5];
    if (tid == 0) scnt = 0u;
    __syncthreads();

    const uint2* __restrict__ Et = g_E[t];

    const int f4 = blockIdx.x * (ETPB * 2) + tid * 2;
    float4 p0 = points4[f4];
    float4 p1 = points4[f4 + 1];

    float x[EPPT];
    x[0] = p0.x;  x[1] = p0.y;  x[2] = p0.z;  x[3] = p0.w;
    x[4] = p1.x;  x[5] = p1.y;  x[6] = p1.z;  x[7] = p1.w;

    // -- phase 1: bins + fractions (no memory deps) --
    uint32_t bin[EPPT];
    float    tt[EPPT];
    #pragma unroll
    for (int k = 0; k < EPPT; k++) {
        float v = __saturatef(x[k]);
        float w;
        asm("fma.rz.f32 %0, %1, 0f46800000, 0f4B000000;" : "=f"(w) : "f"(v));
        bin[k] = ((uint32_t)__float_as_int(w)) & 0x7FFFu;
        float binf = w - 8388608.0f;                 // (float)bin, exact
        tt[k] = fmaf(v, 16384.0f, -binf);            // exact fraction
    }

    // -- phase 2: issue all 8 loads back-to-back (MLP=8) --
    uint2 e[EPPT];
    #pragma unroll
    for (int k = 0; k < EPPT; k++)
        e[k] = __ldg(Et + bin[k]);

    // -- phase 3: interpolate + collect unsafe mask --
    float r[EPPT];
    uint32_t m8 = 0u;
    #pragma unroll
    for (int k = 0; k < EPPT; k++) {
        float F0 = __uint_as_float(e[k].x);
        float dF = __uint_as_float(e[k].y & 0xFFFF0000u);
        r[k] = fmaf(tt[k], dF, F0);
        m8 |= (e[k].y & 1u) << k;
    }

    float4 o0, o1;
    o0.x = r[0];  o0.y = r[1];  o0.z = r[2];  o0.w = r[3];
    o1.x = r[4];  o1.y = r[5];  o1.z = r[6];  o1.w = r[7];
    float4* __restrict__ op = out4 + ((size_t)t * n_points) / 4;
    op[f4]     = o0;
    op[f4 + 1] = o1;

    // -- one warp scan + one shared atomic for compaction --
    int cnt = __popc(m8);
    int pre = cnt;
    #pragma unroll
    for (int d = 1; d < 32; d <<= 1) {
        int v = __shfl_up_sync(0xffffffffu, pre, d);
        if (lane >= d) pre += v;
    }
    int tot = __shfl_sync(0xffffffffu, pre, 31);
    if (tot) {
        uint32_t base = 0;
        if (lane == 31) base = atomicAdd(&scnt, (uint32_t)tot);
        base = __shfl_sync(0xffffffffu, base, 31);
        uint32_t slot = base + (uint32_t)(pre - cnt);
        const uint32_t pbase = (uint32_t)(f4 * 4);
        uint32_t mm = m8;
        while (mm) {
            int k = __ffs(mm) - 1;
            mm &= mm - 1u;
            slist[slot++] = pbase + (uint32_t)k;
        }
    }

    __syncthreads();

    // -- exact 32-step recurrence for this block's unsafe points --
    const uint32_t n = scnt;
    const uint32_t sbase =
        (uint32_t)__cvta_generic_to_shared(tab) + (uint32_t)(lane * 8);

    for (uint32_t j = tid; j < n; j += ETPB) {
        uint32_t i = slist[j];
        float xx = __ldg(points + i);
        #pragma unroll
        for (int s = 0; s < NSTEPS; s++) {
            float v = __saturatef(xx);
            float u;
            asm("fma.rz.f32 %0, %1, 0f42000000, 0f4B000000;" : "=f"(u) : "f"(v));
            uint32_t bits = (uint32_t)__float_as_int(u);
            float ea, bp;
            asm("ld.shared.v2.f32 {%0, %1}, [%2];"
                : "=f"(ea), "=f"(bp) : "r"(sbase + (bits << 8)));
            xx = fmaf(ea, xx, bp);
        }
        out[(size_t)t * n_points + i] = xx;
    }
}

extern "C" void kernel_launch(void* const* d_in, const int* in_sizes, int n_in,
                              void* d_out, int out_size) {
    const float* points = (const float*)d_in[0];   // [1, n_points]
    const float* theta  = (const float*)d_in[1];   // [n_theta, 30]
    const float* basis  = (const float*)d_in[2];   // [64, 30]
    float* out = (float*)d_out;                    // [n_theta, 1, n_points]

    const int n_points = in_sizes[0];
    const int n_theta  = in_sizes[1] / DDIM;

    dim3 bgrid((NBIN + 1 + BTPB - 1) / BTPB, n_theta);
    build_kernel<<<bgrid, BTPB>>>(theta, basis);

    dim3 egrid(n_points / (ETPB * EPPT), n_theta);
    eval_kernel<<<egrid, ETPB>>>((const float4*)points, points,
                                 (float4*)out, out, n_points);
}